// round 16
// baseline (speedup 1.0000x reference)
#include <cuda_runtime.h>

#define EPSF 1e-5f
#define BATCH 256
#define C1 20
#define H1 62
#define P1 31
#define C2 40
#define H2 30
#define P2 15
#define C3 60
#define H3 14
#define P3 7
#define CL 80
#define FEAT 5820
#define X2OFF 2940
#define NFC 768
#define HASHN 48
#define SPLITN 16
#define KSPLIT 16
#define KCHUNK 368

// ---------------- scratch (device globals) ------------------------------------
__device__ float d_p1max[BATCH * C1 * P1 * P1];
__device__ float d_p1min[BATCH * C1 * P1 * P1];
__device__ float d_p2max[BATCH * C2 * P2 * P2];
__device__ float d_p2min[BATCH * C2 * P2 * P2];
__device__ float d_p3max[BATCH * C3 * P3 * P3];
__device__ float d_p3min[BATCH * C3 * P3 * P3];
__device__ float d_feat[BATCH * FEAT];           // [256,5820]
__device__ float d_lc[BATCH * CL * 36];          // [256,80,6,6]
__device__ float d_y[BATCH * NFC];               // [256,768]
__device__ float d_ypart[KSPLIT * BATCH * NFC];

__device__ float d_s1[C1], d_q1[C1];
__device__ float d_s2[C2], d_q2[C2];
__device__ float d_s3[C3], d_q3[C3];
__device__ float d_s4[CL], d_q4[CL];
__device__ float d_s5[NFC], d_q5[NFC];

__global__ void zero_stats_kernel() {
    int t = threadIdx.x;
    if (t < C1) { d_s1[t] = 0.f; d_q1[t] = 0.f; }
    if (t < C2) { d_s2[t] = 0.f; d_q2[t] = 0.f; }
    if (t < C3) { d_s3[t] = 0.f; d_q3[t] = 0.f; }
    if (t < CL) { d_s4[t] = 0.f; d_q4[t] = 0.f; }
    if (t < NFC) { d_s5[t] = 0.f; d_q5[t] = 0.f; }
}

__device__ __forceinline__ float wsum(float v) {
    v += __shfl_xor_sync(0xffffffffu, v, 16);
    v += __shfl_xor_sync(0xffffffffu, v, 8);
    v += __shfl_xor_sync(0xffffffffu, v, 4);
    v += __shfl_xor_sync(0xffffffffu, v, 2);
    v += __shfl_xor_sync(0xffffffffu, v, 1);
    return v;
}

// ---------------- conv1: 3x3, 3->20 (COT=10, 2 co-groups), fused stats+pool ---
__global__ void __launch_bounds__(256) conv1_kernel(const float* __restrict__ x,
                                                    const float* __restrict__ w,
                                                    const float* __restrict__ bias) {
    constexpr int COT = 10;
    __shared__ float sw[COT * 27];
    __shared__ float sb[COT];
    __shared__ float swS[8][COT];
    __shared__ float swQ[8][COT];
    int tid = threadIdx.x;
    int lane = tid & 31, warp = tid >> 5;
    int cog = blockIdx.y;
    for (int i = tid; i < COT * 27; i += 256) sw[i] = w[cog * COT * 27 + i];
    if (tid < COT) sb[tid] = bias[cog * COT + tid];
    __syncthreads();

    int b = blockIdx.z;
    int tile = blockIdx.x * 256 + tid;  // 992 active: 16 rowtiles x 62 cols
    bool act = (tile < 16 * H1);
    int col = tile % H1;
    int r0 = (tile / H1) * 4;

    float acc[COT][4];
#pragma unroll
    for (int co = 0; co < COT; co++) {
        float bv = sb[co];
#pragma unroll
        for (int r = 0; r < 4; r++) acc[co][r] = bv;
    }

    const float* xb = x + (long)b * 3 * 64 * 64;
#pragma unroll
    for (int ci = 0; ci < 3; ci++) {
        float in[6][3];
#pragma unroll
        for (int rr = 0; rr < 6; rr++) {
            int rowIdx = r0 + rr;
#pragma unroll
            for (int cc = 0; cc < 3; cc++)
                in[rr][cc] = (rowIdx < 64) ? __ldg(&xb[ci * 4096 + rowIdx * 64 + col + cc]) : 0.f;
        }
#pragma unroll
        for (int kh = 0; kh < 3; kh++) {
#pragma unroll
            for (int kw = 0; kw < 3; kw++) {
#pragma unroll
                for (int co = 0; co < COT; co++) {
                    float wv = sw[co * 27 + ci * 9 + kh * 3 + kw];
#pragma unroll
                    for (int r = 0; r < 4; r++)
                        acc[co][r] += wv * in[r + kh][kw];
                }
            }
        }
    }

    bool rv0 = act && (r0 + 0 < H1), rv1 = act && (r0 + 1 < H1);
    bool rv2 = act && (r0 + 2 < H1), rv3 = act && (r0 + 3 < H1);
    int pcol = col >> 1;
    bool store0 = act && ((lane & 1) == 0) && (r0 + 1 < H1);
    bool store1 = act && ((lane & 1) == 0) && (r0 + 3 < H1);
    long pbase = ((long)b * C1 + cog * COT) * (P1 * P1) + (r0 >> 1) * P1 + pcol;

#pragma unroll
    for (int co = 0; co < COT; co++) {
        float a0 = acc[co][0], a1 = acc[co][1], a2 = acc[co][2], a3 = acc[co][3];
        float s = (rv0 ? a0 : 0.f) + (rv1 ? a1 : 0.f) + (rv2 ? a2 : 0.f) + (rv3 ? a3 : 0.f);
        float q = (rv0 ? a0 * a0 : 0.f) + (rv1 ? a1 * a1 : 0.f) +
                  (rv2 ? a2 * a2 : 0.f) + (rv3 ? a3 * a3 : 0.f);
        s = wsum(s); q = wsum(q);
        if (lane == 0) { swS[warp][co] = s; swQ[warp][co] = q; }
        float m0 = fmaxf(a0, a1), n0 = fminf(a0, a1);
        float m1 = fmaxf(a2, a3), n1 = fminf(a2, a3);
        m0 = fmaxf(m0, __shfl_xor_sync(0xffffffffu, m0, 1));
        n0 = fminf(n0, __shfl_xor_sync(0xffffffffu, n0, 1));
        m1 = fmaxf(m1, __shfl_xor_sync(0xffffffffu, m1, 1));
        n1 = fminf(n1, __shfl_xor_sync(0xffffffffu, n1, 1));
        long pp = pbase + (long)co * (P1 * P1);
        if (store0) { d_p1max[pp] = m0; d_p1min[pp] = n0; }
        if (store1) { d_p1max[pp + P1] = m1; d_p1min[pp + P1] = n1; }
    }
    __syncthreads();
    if (tid < COT) {
        float s = 0.f;
#pragma unroll
        for (int wdx = 0; wdx < 8; wdx++) s += swS[wdx][tid];
        atomicAdd(&d_s1[cog * COT + tid], s);
    } else if (tid >= 32 && tid < 32 + COT) {
        float q = 0.f;
#pragma unroll
        for (int wdx = 0; wdx < 8; wdx++) q += swQ[wdx][tid - 32];
        atomicAdd(&d_q1[cog * COT + tid - 32], q);
    }
}

// ---- 2x2 conv, 2-row tiles, scalar weight LDS, fused bn+stats+pool -----------
// STAGE 2: COT=10, blockDim 256 (240 active), grid (2, 4, 256).
// STAGE 3: COT=12, blockDim 224 (196 active = 2 imgs x 98 tiles), grid (1, 5, 128).
template <int STAGE>
__global__ void conv2x2_kernel(const float* __restrict__ w,
                               const float* __restrict__ bias,
                               const float* __restrict__ gIn,
                               const float* __restrict__ bIn) {
    constexpr int Cin  = (STAGE == 2) ? C1 : C2;
    constexpr int Cout = (STAGE == 2) ? C2 : C3;
    constexpr int Hin  = (STAGE == 2) ? P1 : P2;
    constexpr int Hout = (STAGE == 2) ? H2 : H3;
    constexpr int Pout = (STAGE == 2) ? P2 : P3;
    constexpr int HPrev = (STAGE == 2) ? H1 : H2;
    constexpr int COT  = (STAGE == 2) ? 10 : 12;
    constexpr int NTILE = (Hout / 2) * Hout;  // rowpairs * cols
    constexpr int NWARPS = (STAGE == 2) ? 8 : 7;
    const float* inmax = (STAGE == 2) ? d_p1max : d_p2max;
    const float* inmin = (STAGE == 2) ? d_p1min : d_p2min;
    const float* sIn   = (STAGE == 2) ? d_s1 : d_s2;
    const float* qIn   = (STAGE == 2) ? d_q1 : d_q2;
    float* pmaxb = (STAGE == 2) ? d_p2max : d_p3max;
    float* pminb = (STAGE == 2) ? d_p2min : d_p3min;
    float* sAcc  = (STAGE == 2) ? d_s2 : d_s3;
    float* qAcc  = (STAGE == 2) ? d_q2 : d_q3;

    __shared__ float sw[COT * Cin * 4];
    __shared__ float sb[COT];
    __shared__ float scIn[Cin], shIn[Cin];
    __shared__ float swS[NWARPS][COT];
    __shared__ float swQ[NWARPS][COT];
    int tid = threadIdx.x;
    int lane = tid & 31, warp = tid >> 5;
    int cog = blockIdx.y;
    for (int i = tid; i < COT * Cin * 4; i += blockDim.x)
        sw[i] = w[(long)cog * COT * Cin * 4 + i];
    if (tid < COT) sb[tid] = bias[cog * COT + tid];
    if (tid >= 64 && tid < 64 + Cin) {
        int c = tid - 64;
        constexpr float invN = 1.f / ((float)BATCH * HPrev * HPrev);
        float mean = sIn[c] * invN;
        float var = qIn[c] * invN - mean * mean;
        float rstd = rsqrtf(var + EPSF);
        float sc = __ldg(&gIn[c]) * rstd;
        scIn[c] = sc;
        shIn[c] = __ldg(&bIn[c]) - mean * sc;
    }
    __syncthreads();

    int b, tile;
    bool act;
    if (STAGE == 2) {
        b = blockIdx.z;
        tile = blockIdx.x * 240 + tid;
        act = (tid < 240) && (tile < NTILE);
        if (!act) tile = 0;
    } else {
        int img = tid / 98;
        tile = tid % 98;
        act = (tid < 196);
        b = blockIdx.z * 2 + (act ? img : 0);
    }
    int col = tile % Hout;
    int rp = tile / Hout;       // rowpair index
    int r0 = rp * 2;

    float acc[COT][2];
#pragma unroll
    for (int co = 0; co < COT; co++) {
        float bv = sb[co];
        acc[co][0] = bv; acc[co][1] = bv;
    }

#pragma unroll 2
    for (int ci = 0; ci < Cin; ci++) {
        float sc = scIn[ci], sh = shIn[ci];
        const float* src = (sc >= 0.f) ? inmax : inmin;
        const float* p = src + ((long)b * Cin + ci) * Hin * Hin + r0 * Hin + col;
        float inv[3][2];
#pragma unroll
        for (int rr = 0; rr < 3; rr++) {
            float v0 = act ? __ldg(&p[rr * Hin]) : 0.f;
            float v1 = act ? __ldg(&p[rr * Hin + 1]) : 0.f;
            inv[rr][0] = fmaxf(fmaf(v0, sc, sh), 0.f);
            inv[rr][1] = fmaxf(fmaf(v1, sc, sh), 0.f);
        }
#pragma unroll
        for (int kh = 0; kh < 2; kh++) {
#pragma unroll
            for (int kw = 0; kw < 2; kw++) {
#pragma unroll
                for (int co = 0; co < COT; co++) {
                    float wv = sw[co * Cin * 4 + ci * 4 + kh * 2 + kw];
                    acc[co][0] += wv * inv[kh][kw];
                    acc[co][1] += wv * inv[kh + 1][kw];
                }
            }
        }
    }

    int pcol = col >> 1;
    bool store0 = act && ((lane & 1) == 0);
    long pbase = ((long)b * Cout + cog * COT) * (Pout * Pout) + rp * Pout + pcol;

#pragma unroll
    for (int co = 0; co < COT; co++) {
        float a0 = acc[co][0], a1 = acc[co][1];
        float s = act ? (a0 + a1) : 0.f;
        float q = act ? (a0 * a0 + a1 * a1) : 0.f;
        s = wsum(s); q = wsum(q);
        if (lane == 0) { swS[warp][co] = s; swQ[warp][co] = q; }
        float m0 = fmaxf(a0, a1), n0 = fminf(a0, a1);
        m0 = fmaxf(m0, __shfl_xor_sync(0xffffffffu, m0, 1));
        n0 = fminf(n0, __shfl_xor_sync(0xffffffffu, n0, 1));
        long pp = pbase + (long)co * (Pout * Pout);
        if (store0) { pmaxb[pp] = m0; pminb[pp] = n0; }
    }
    __syncthreads();
    if (tid < COT) {
        float s = 0.f;
#pragma unroll
        for (int wdx = 0; wdx < NWARPS; wdx++) s += swS[wdx][tid];
        atomicAdd(&sAcc[cog * COT + tid], s);
    } else if (tid >= 32 && tid < 32 + COT) {
        float q = 0.f;
#pragma unroll
        for (int wdx = 0; wdx < NWARPS; wdx++) q += swQ[wdx][tid - 32];
        atomicAdd(&qAcc[cog * COT + tid - 32], q);
    }
}

// ---------------- bn apply stage3 -> feat x1 ----------------------------------
__global__ void bnapply3_kernel(const float* __restrict__ g,
                                const float* __restrict__ bb) {
    constexpr float invN = 1.f / ((float)BATCH * H3 * H3);
    int idx = blockIdx.x * blockDim.x + threadIdx.x;
    if (idx >= BATCH * C3 * 49) return;
    int c = (idx / 49) % C3;
    float mean = d_s3[c] * invN;
    float var = d_q3[c] * invN - mean * mean;
    float rstd = rsqrtf(var + EPSF);
    float scale = __ldg(&g[c]) * rstd;
    float shift = __ldg(&bb[c]) - mean * scale;
    float v = (scale >= 0.f) ? d_p3max[idx] : d_p3min[idx];
    float r = fmaxf(fmaf(v, scale, shift), 0.f);
    int b = idx / (C3 * 49), rr = idx % (C3 * 49);
    d_feat[(long)b * FEAT + rr] = r;
}

// ---------------- LocallyConnected2d ------------------------------------------
#define LC_BT 4
__global__ void lc_kernel(const float* __restrict__ w, const float* __restrict__ bias) {
    __shared__ float sh[LC_BT * 2940];
    int b0 = blockIdx.x * LC_BT;
    int t = threadIdx.x;  // 0..239
    for (int idx = t; idx < LC_BT * 2940; idx += 240) {
        int bb = idx / 2940, off = idx % 2940;
        sh[idx] = d_feat[(long)(b0 + bb) * FEAT + off];
    }
    __syncthreads();
    int go = blockIdx.y * 240 + t;  // 0..2879
    int o = go / 36, ij = go % 36, i = ij / 6, j = ij % 6;
    float bv = __ldg(&bias[o * 36 + ij]);
    float acc[LC_BT];
#pragma unroll
    for (int bb = 0; bb < LC_BT; bb++) acc[bb] = bv;
    const float* wp = w + (long)o * 60 * 144 + ij * 4;
    for (int c = 0; c < 60; c++) {
        int hb = c * 49 + i * 7 + j;
        float w0 = __ldg(&wp[c * 144 + 0]);
        float w1 = __ldg(&wp[c * 144 + 1]);
        float w2 = __ldg(&wp[c * 144 + 2]);
        float w3 = __ldg(&wp[c * 144 + 3]);
#pragma unroll
        for (int bb = 0; bb < LC_BT; bb++) {
            const float* hp = sh + bb * 2940 + hb;
            acc[bb] += hp[0] * w0 + hp[1] * w1 + hp[7] * w2 + hp[8] * w3;
        }
    }
    float ps = 0.f, pq = 0.f;
#pragma unroll
    for (int bb = 0; bb < LC_BT; bb++) {
        d_lc[((long)(b0 + bb) * CL + o) * 36 + ij] = acc[bb];
        ps += acc[bb];
        pq += acc[bb] * acc[bb];
    }
    atomicAdd(&d_s4[o], ps);
    atomicAdd(&d_q4[o], pq);
}

__global__ void lcbn_kernel(const float* __restrict__ g, const float* __restrict__ bb) {
    int idx = blockIdx.x * blockDim.x + threadIdx.x;
    if (idx >= BATCH * CL * 36) return;
    int b = idx / (CL * 36), r = idx % (CL * 36), o = r / 36;
    const float invN = 1.f / (BATCH * 36);
    float mean = d_s4[o] * invN;
    float var = d_q4[o] * invN - mean * mean;
    float rstd = rsqrtf(var + EPSF);
    float scale = __ldg(&g[o]) * rstd;
    float shift = __ldg(&bb[o]) - mean * scale;
    d_feat[(long)b * FEAT + X2OFF + r] = fmaxf(fmaf(d_lc[idx], scale, shift), 0.f);
}

// ---------------- FC: split-K GEMM, 128x128 tiles, 8x8 microtile, BK=16, db ---
// Per k-step: 4 LDS.128 (16 crossbar cyc/warp) per 64 FFMA (32 cyc) -> FMA-bound.
__global__ void __launch_bounds__(256) fc_kernel(const float* __restrict__ fw) {
    __shared__ float As[2][16][132];  // [buf][k][m]
    __shared__ float Bs[2][16][132];  // [buf][k][n]
    int n0 = blockIdx.x * 128, m0 = blockIdx.y * 128;
    int kz = blockIdx.z;
    int kstart = kz * KCHUNK;
    int kend = min(FEAT, kstart + KCHUNK);
    int tid = threadIdx.x;
    int tx = tid % 16, ty = tid / 16;

    float acc[8][8];
#pragma unroll
    for (int i = 0; i < 8; i++)
#pragma unroll
        for (int j = 0; j < 8; j++) acc[i][j] = 0.f;

    int lr = tid / 4;        // 0..63
    int lk = (tid % 4) * 4;  // 0,4,8,12

    // preload tile 0
    {
        int kk = kstart + lk;
        bool kok = (kk < kend);
#pragma unroll
        for (int half = 0; half < 2; half++) {
            int r = lr + half * 64;
            float4 av = kok ? *(const float4*)&d_feat[(long)(m0 + r) * FEAT + kk]
                            : make_float4(0.f, 0.f, 0.f, 0.f);
            float4 bv = kok ? *(const float4*)&fw[(long)(n0 + r) * FEAT + kk]
                            : make_float4(0.f, 0.f, 0.f, 0.f);
            As[0][lk + 0][r] = av.x; As[0][lk + 1][r] = av.y;
            As[0][lk + 2][r] = av.z; As[0][lk + 3][r] = av.w;
            Bs[0][lk + 0][r] = bv.x; Bs[0][lk + 1][r] = bv.y;
            Bs[0][lk + 2][r] = bv.z; Bs[0][lk + 3][r] = bv.w;
        }
    }
    __syncthreads();

    int buf = 0;
    for (int k0 = kstart; k0 < kend; k0 += 16) {
        int nk0 = k0 + 16;
        bool has = (nk0 < kend);
        float4 pav[2], pbv[2];
        if (has) {
            int kk = nk0 + lk;
            bool kok = (kk < kend);
#pragma unroll
            for (int half = 0; half < 2; half++) {
                int r = lr + half * 64;
                pav[half] = kok ? *(const float4*)&d_feat[(long)(m0 + r) * FEAT + kk]
                                : make_float4(0.f, 0.f, 0.f, 0.f);
                pbv[half] = kok ? *(const float4*)&fw[(long)(n0 + r) * FEAT + kk]
                                : make_float4(0.f, 0.f, 0.f, 0.f);
            }
        }
#pragma unroll
        for (int k = 0; k < 16; k++) {
            float4 a0 = *(const float4*)&As[buf][k][ty * 8];
            float4 a1 = *(const float4*)&As[buf][k][ty * 8 + 4];
            float4 b0 = *(const float4*)&Bs[buf][k][tx * 8];
            float4 b1 = *(const float4*)&Bs[buf][k][tx * 8 + 4];
            float av[8] = {a0.x, a0.y, a0.z, a0.w, a1.x, a1.y, a1.z, a1.w};
            float bvv[8] = {b0.x, b0.y, b0.z, b0.w, b1.x, b1.y, b1.z, b1.w};
#pragma unroll
            for (int i = 0; i < 8; i++)
#pragma unroll
                for (int j = 0; j < 8; j++)
                    acc[i][j] += av[i] * bvv[j];
        }
        if (has) {
            int nb = buf ^ 1;
#pragma unroll
            for (int half = 0; half < 2; half++) {
                int r = lr + half * 64;
                As[nb][lk + 0][r] = pav[half].x; As[nb][lk + 1][r] = pav[half].y;
                As[nb][lk + 2][r] = pav[half].z; As[nb][lk + 3][r] = pav[half].w;
                Bs[nb][lk + 0][r] = pbv[half].x; Bs[nb][lk + 1][r] = pbv[half].y;
                Bs[nb][lk + 2][r] = pbv[half].z; Bs[nb][lk + 3][r] = pbv[half].w;
            }
        }
        __syncthreads();
        buf ^= 1;
    }
    float* yp = d_ypart + (long)kz * BATCH * NFC;
#pragma unroll
    for (int i = 0; i < 8; i++) {
        int m = m0 + ty * 8 + i;
#pragma unroll
        for (int j = 0; j < 8; j++)
            yp[(long)m * NFC + n0 + tx * 8 + j] = acc[i][j];
    }
}

__global__ void fc_combine_kernel(const float* __restrict__ fb) {
    int idx = blockIdx.x * blockDim.x + threadIdx.x;
    if (idx >= BATCH * NFC) return;
    int n = idx % NFC;
    float v = __ldg(&fb[n]);
#pragma unroll
    for (int kz = 0; kz < KSPLIT; kz++)
        v += d_ypart[(long)kz * BATCH * NFC + idx];
    d_y[idx] = v;
    atomicAdd(&d_s5[n], v);
    atomicAdd(&d_q5[n], v * v);
}

__global__ void fuse_kernel(const float* __restrict__ g, const float* __restrict__ bb,
                            const float* __restrict__ fw, const float* __restrict__ fbias,
                            float* __restrict__ out) {
    int idx = blockIdx.x * blockDim.x + threadIdx.x;
    if (idx >= BATCH * HASHN) return;
    int b = idx / HASHN, h = idx % HASHN;
    float acc = __ldg(&fbias[h]);
    const float invN = 1.f / BATCH;
#pragma unroll
    for (int s = 0; s < SPLITN; s++) {
        int f = h * SPLITN + s;
        float mean = d_s5[f] * invN;
        float var = d_q5[f] * invN - mean * mean;
        float rstd = rsqrtf(var + EPSF);
        float scale = __ldg(&g[f]) * rstd;
        float shift = __ldg(&bb[f]) - mean * scale;
        float v = fmaxf(fmaf(d_y[(long)b * NFC + f], scale, shift), 0.f);
        acc += v * __ldg(&fw[h * SPLITN + s]);
    }
    out[idx] = acc;
}

// ---------------- launch ------------------------------------------------------
extern "C" void kernel_launch(void* const* d_in, const int* in_sizes, int n_in,
                              void* d_out, int out_size) {
    const float* x = (const float*)d_in[0];
    const float* c1w = (const float*)d_in[1];
    const float* c1b = (const float*)d_in[2];
    const float* g1 = (const float*)d_in[3];
    const float* b1 = (const float*)d_in[4];
    const float* c2w = (const float*)d_in[5];
    const float* c2b = (const float*)d_in[6];
    const float* g2 = (const float*)d_in[7];
    const float* b2 = (const float*)d_in[8];
    const float* c3w = (const float*)d_in[9];
    const float* c3b = (const float*)d_in[10];
    const float* g3 = (const float*)d_in[11];
    const float* b3 = (const float*)d_in[12];
    const float* lcw = (const float*)d_in[13];
    const float* lcb = (const float*)d_in[14];
    const float* g4 = (const float*)d_in[15];
    const float* b4 = (const float*)d_in[16];
    const float* fcw = (const float*)d_in[17];
    const float* fcb = (const float*)d_in[18];
    const float* g5 = (const float*)d_in[19];
    const float* b5 = (const float*)d_in[20];
    const float* fw = (const float*)d_in[21];
    const float* fbias = (const float*)d_in[22];
    float* out = (float*)d_out;

    zero_stats_kernel<<<1, 1024>>>();

    // conv1: 992 tiles, 2 co-groups of 10
    conv1_kernel<<<dim3(4, 2, BATCH), 256>>>(x, c1w, c1b);
    // conv2 (applies bn1 on input): 450 2-row tiles, 4 co-groups of 10
    conv2x2_kernel<2><<<dim3(2, 4, BATCH), 256>>>(c2w, c2b, g1, b1);
    // conv3 (applies bn2 on input): 98 2-row tiles, 5 co-groups of 12, 2 imgs/block
    conv2x2_kernel<3><<<dim3(1, 5, BATCH / 2), 224>>>(c3w, c3b, g2, b2);
    // bn3 -> feat x1
    bnapply3_kernel<<<(BATCH * C3 * 49 + 255) / 256, 256>>>(g3, b3);

    lc_kernel<<<dim3(BATCH / LC_BT, 12), 240>>>(lcw, lcb);
    lcbn_kernel<<<(BATCH * CL * 36 + 255) / 256, 256>>>(g4, b4);

    // FC gemm: 128x128 tiles, 8x8 microtile, BK=16, split-K 16, double-buffered
    fc_kernel<<<dim3(NFC / 128, BATCH / 128, KSPLIT), 256>>>(fcw);
    fc_combine_kernel<<<(BATCH * NFC + 255) / 256, 256>>>(fcb);
    fuse_kernel<<<(BATCH * HASHN + 255) / 256, 256>>>(g5, b5, fw, fbias, out);
}

// round 17
// speedup vs baseline: 1.0500x; 1.0500x over previous
#include <cuda_runtime.h>

#define EPSF 1e-5f
#define BATCH 256
#define C1 20
#define H1 62
#define P1 31
#define C2 40
#define H2 30
#define P2 15
#define C3 60
#define H3 14
#define P3 7
#define CL 80
#define FEAT 5820
#define X2OFF 2940
#define NFC 768
#define HASHN 48
#define SPLITN 16
#define KSPLIT 8
#define KCHUNK 736

// ---------------- scratch (device globals) ------------------------------------
__device__ float d_p1max[BATCH * C1 * P1 * P1];
__device__ float d_p1min[BATCH * C1 * P1 * P1];
__device__ float d_p2max[BATCH * C2 * P2 * P2];
__device__ float d_p2min[BATCH * C2 * P2 * P2];
__device__ float d_p3max[BATCH * C3 * P3 * P3];
__device__ float d_p3min[BATCH * C3 * P3 * P3];
__device__ float d_feat[BATCH * FEAT];           // [256,5820]
__device__ float d_lc[BATCH * CL * 36];          // [256,80,6,6]
__device__ float d_y[BATCH * NFC];               // [256,768]
__device__ float d_ypart[KSPLIT * BATCH * NFC];

__device__ float d_s1[C1], d_q1[C1];
__device__ float d_s2[C2], d_q2[C2];
__device__ float d_s3[C3], d_q3[C3];
__device__ float d_s4[CL], d_q4[CL];
__device__ float d_s5[NFC], d_q5[NFC];

__global__ void zero_stats_kernel() {
    int t = threadIdx.x;
    if (t < C1) { d_s1[t] = 0.f; d_q1[t] = 0.f; }
    if (t < C2) { d_s2[t] = 0.f; d_q2[t] = 0.f; }
    if (t < C3) { d_s3[t] = 0.f; d_q3[t] = 0.f; }
    if (t < CL) { d_s4[t] = 0.f; d_q4[t] = 0.f; }
    if (t < NFC) { d_s5[t] = 0.f; d_q5[t] = 0.f; }
}

__device__ __forceinline__ float wsum(float v) {
    v += __shfl_xor_sync(0xffffffffu, v, 16);
    v += __shfl_xor_sync(0xffffffffu, v, 8);
    v += __shfl_xor_sync(0xffffffffu, v, 4);
    v += __shfl_xor_sync(0xffffffffu, v, 2);
    v += __shfl_xor_sync(0xffffffffu, v, 1);
    return v;
}

// ---------------- conv1: 3x3, 3->20 (COT=10, 2 co-groups), fused stats+pool ---
__global__ void __launch_bounds__(256) conv1_kernel(const float* __restrict__ x,
                                                    const float* __restrict__ w,
                                                    const float* __restrict__ bias) {
    constexpr int COT = 10;
    __shared__ float sw[COT * 27];
    __shared__ float sb[COT];
    __shared__ float swS[8][COT];
    __shared__ float swQ[8][COT];
    int tid = threadIdx.x;
    int lane = tid & 31, warp = tid >> 5;
    int cog = blockIdx.y;
    for (int i = tid; i < COT * 27; i += 256) sw[i] = w[cog * COT * 27 + i];
    if (tid < COT) sb[tid] = bias[cog * COT + tid];
    __syncthreads();

    int b = blockIdx.z;
    int tile = blockIdx.x * 256 + tid;  // 992 active: 16 rowtiles x 62 cols
    bool act = (tile < 16 * H1);
    int col = tile % H1;
    int r0 = (tile / H1) * 4;

    float acc[COT][4];
#pragma unroll
    for (int co = 0; co < COT; co++) {
        float bv = sb[co];
#pragma unroll
        for (int r = 0; r < 4; r++) acc[co][r] = bv;
    }

    const float* xb = x + (long)b * 3 * 64 * 64;
#pragma unroll
    for (int ci = 0; ci < 3; ci++) {
        float in[6][3];
#pragma unroll
        for (int rr = 0; rr < 6; rr++) {
            int rowIdx = r0 + rr;
#pragma unroll
            for (int cc = 0; cc < 3; cc++)
                in[rr][cc] = (rowIdx < 64) ? __ldg(&xb[ci * 4096 + rowIdx * 64 + col + cc]) : 0.f;
        }
#pragma unroll
        for (int kh = 0; kh < 3; kh++) {
#pragma unroll
            for (int kw = 0; kw < 3; kw++) {
#pragma unroll
                for (int co = 0; co < COT; co++) {
                    float wv = sw[co * 27 + ci * 9 + kh * 3 + kw];
#pragma unroll
                    for (int r = 0; r < 4; r++)
                        acc[co][r] += wv * in[r + kh][kw];
                }
            }
        }
    }

    bool rv0 = act && (r0 + 0 < H1), rv1 = act && (r0 + 1 < H1);
    bool rv2 = act && (r0 + 2 < H1), rv3 = act && (r0 + 3 < H1);
    int pcol = col >> 1;
    bool store0 = act && ((lane & 1) == 0) && (r0 + 1 < H1);
    bool store1 = act && ((lane & 1) == 0) && (r0 + 3 < H1);
    long pbase = ((long)b * C1 + cog * COT) * (P1 * P1) + (r0 >> 1) * P1 + pcol;

#pragma unroll
    for (int co = 0; co < COT; co++) {
        float a0 = acc[co][0], a1 = acc[co][1], a2 = acc[co][2], a3 = acc[co][3];
        float s = (rv0 ? a0 : 0.f) + (rv1 ? a1 : 0.f) + (rv2 ? a2 : 0.f) + (rv3 ? a3 : 0.f);
        float q = (rv0 ? a0 * a0 : 0.f) + (rv1 ? a1 * a1 : 0.f) +
                  (rv2 ? a2 * a2 : 0.f) + (rv3 ? a3 * a3 : 0.f);
        s = wsum(s); q = wsum(q);
        if (lane == 0) { swS[warp][co] = s; swQ[warp][co] = q; }
        float m0 = fmaxf(a0, a1), n0 = fminf(a0, a1);
        float m1 = fmaxf(a2, a3), n1 = fminf(a2, a3);
        m0 = fmaxf(m0, __shfl_xor_sync(0xffffffffu, m0, 1));
        n0 = fminf(n0, __shfl_xor_sync(0xffffffffu, n0, 1));
        m1 = fmaxf(m1, __shfl_xor_sync(0xffffffffu, m1, 1));
        n1 = fminf(n1, __shfl_xor_sync(0xffffffffu, n1, 1));
        long pp = pbase + (long)co * (P1 * P1);
        if (store0) { d_p1max[pp] = m0; d_p1min[pp] = n0; }
        if (store1) { d_p1max[pp + P1] = m1; d_p1min[pp + P1] = n1; }
    }
    __syncthreads();
    if (tid < COT) {
        float s = 0.f;
#pragma unroll
        for (int wdx = 0; wdx < 8; wdx++) s += swS[wdx][tid];
        atomicAdd(&d_s1[cog * COT + tid], s);
    } else if (tid >= 32 && tid < 32 + COT) {
        float q = 0.f;
#pragma unroll
        for (int wdx = 0; wdx < 8; wdx++) q += swQ[wdx][tid - 32];
        atomicAdd(&d_q1[cog * COT + tid - 32], q);
    }
}

// ---- 2x2 conv, 2-row tiles, scalar weight LDS, fused bn+stats+pool -----------
// STAGE 2: COT=10, blockDim 256 (240 active), grid (2, 4, 256).
// STAGE 3: COT=12, blockDim 224 (196 active = 2 imgs x 98 tiles), grid (1, 5, 128).
template <int STAGE>
__global__ void conv2x2_kernel(const float* __restrict__ w,
                               const float* __restrict__ bias,
                               const float* __restrict__ gIn,
                               const float* __restrict__ bIn) {
    constexpr int Cin  = (STAGE == 2) ? C1 : C2;
    constexpr int Cout = (STAGE == 2) ? C2 : C3;
    constexpr int Hin  = (STAGE == 2) ? P1 : P2;
    constexpr int Hout = (STAGE == 2) ? H2 : H3;
    constexpr int Pout = (STAGE == 2) ? P2 : P3;
    constexpr int HPrev = (STAGE == 2) ? H1 : H2;
    constexpr int COT  = (STAGE == 2) ? 10 : 12;
    constexpr int NTILE = (Hout / 2) * Hout;  // rowpairs * cols
    constexpr int NWARPS = (STAGE == 2) ? 8 : 7;
    const float* inmax = (STAGE == 2) ? d_p1max : d_p2max;
    const float* inmin = (STAGE == 2) ? d_p1min : d_p2min;
    const float* sIn   = (STAGE == 2) ? d_s1 : d_s2;
    const float* qIn   = (STAGE == 2) ? d_q1 : d_q2;
    float* pmaxb = (STAGE == 2) ? d_p2max : d_p3max;
    float* pminb = (STAGE == 2) ? d_p2min : d_p3min;
    float* sAcc  = (STAGE == 2) ? d_s2 : d_s3;
    float* qAcc  = (STAGE == 2) ? d_q2 : d_q3;

    __shared__ float sw[COT * Cin * 4];
    __shared__ float sb[COT];
    __shared__ float scIn[Cin], shIn[Cin];
    __shared__ float swS[NWARPS][COT];
    __shared__ float swQ[NWARPS][COT];
    int tid = threadIdx.x;
    int lane = tid & 31, warp = tid >> 5;
    int cog = blockIdx.y;
    for (int i = tid; i < COT * Cin * 4; i += blockDim.x)
        sw[i] = w[(long)cog * COT * Cin * 4 + i];
    if (tid < COT) sb[tid] = bias[cog * COT + tid];
    if (tid >= 64 && tid < 64 + Cin) {
        int c = tid - 64;
        constexpr float invN = 1.f / ((float)BATCH * HPrev * HPrev);
        float mean = sIn[c] * invN;
        float var = qIn[c] * invN - mean * mean;
        float rstd = rsqrtf(var + EPSF);
        float sc = __ldg(&gIn[c]) * rstd;
        scIn[c] = sc;
        shIn[c] = __ldg(&bIn[c]) - mean * sc;
    }
    __syncthreads();

    int b, tile;
    bool act;
    if (STAGE == 2) {
        b = blockIdx.z;
        tile = blockIdx.x * 240 + tid;
        act = (tid < 240) && (tile < NTILE);
        if (!act) tile = 0;
    } else {
        int img = tid / 98;
        tile = tid % 98;
        act = (tid < 196);
        b = blockIdx.z * 2 + (act ? img : 0);
    }
    int col = tile % Hout;
    int rp = tile / Hout;       // rowpair index
    int r0 = rp * 2;

    float acc[COT][2];
#pragma unroll
    for (int co = 0; co < COT; co++) {
        float bv = sb[co];
        acc[co][0] = bv; acc[co][1] = bv;
    }

#pragma unroll 2
    for (int ci = 0; ci < Cin; ci++) {
        float sc = scIn[ci], sh = shIn[ci];
        const float* src = (sc >= 0.f) ? inmax : inmin;
        const float* p = src + ((long)b * Cin + ci) * Hin * Hin + r0 * Hin + col;
        float inv[3][2];
#pragma unroll
        for (int rr = 0; rr < 3; rr++) {
            float v0 = act ? __ldg(&p[rr * Hin]) : 0.f;
            float v1 = act ? __ldg(&p[rr * Hin + 1]) : 0.f;
            inv[rr][0] = fmaxf(fmaf(v0, sc, sh), 0.f);
            inv[rr][1] = fmaxf(fmaf(v1, sc, sh), 0.f);
        }
#pragma unroll
        for (int kh = 0; kh < 2; kh++) {
#pragma unroll
            for (int kw = 0; kw < 2; kw++) {
#pragma unroll
                for (int co = 0; co < COT; co++) {
                    float wv = sw[co * Cin * 4 + ci * 4 + kh * 2 + kw];
                    acc[co][0] += wv * inv[kh][kw];
                    acc[co][1] += wv * inv[kh + 1][kw];
                }
            }
        }
    }

    int pcol = col >> 1;
    bool store0 = act && ((lane & 1) == 0);
    long pbase = ((long)b * Cout + cog * COT) * (Pout * Pout) + rp * Pout + pcol;

#pragma unroll
    for (int co = 0; co < COT; co++) {
        float a0 = acc[co][0], a1 = acc[co][1];
        float s = act ? (a0 + a1) : 0.f;
        float q = act ? (a0 * a0 + a1 * a1) : 0.f;
        s = wsum(s); q = wsum(q);
        if (lane == 0) { swS[warp][co] = s; swQ[warp][co] = q; }
        float m0 = fmaxf(a0, a1), n0 = fminf(a0, a1);
        m0 = fmaxf(m0, __shfl_xor_sync(0xffffffffu, m0, 1));
        n0 = fminf(n0, __shfl_xor_sync(0xffffffffu, n0, 1));
        long pp = pbase + (long)co * (Pout * Pout);
        if (store0) { pmaxb[pp] = m0; pminb[pp] = n0; }
    }
    __syncthreads();
    if (tid < COT) {
        float s = 0.f;
#pragma unroll
        for (int wdx = 0; wdx < NWARPS; wdx++) s += swS[wdx][tid];
        atomicAdd(&sAcc[cog * COT + tid], s);
    } else if (tid >= 32 && tid < 32 + COT) {
        float q = 0.f;
#pragma unroll
        for (int wdx = 0; wdx < NWARPS; wdx++) q += swQ[wdx][tid - 32];
        atomicAdd(&qAcc[cog * COT + tid - 32], q);
    }
}

// ---------------- bn apply stage3 -> feat x1 ----------------------------------
__global__ void bnapply3_kernel(const float* __restrict__ g,
                                const float* __restrict__ bb) {
    constexpr float invN = 1.f / ((float)BATCH * H3 * H3);
    int idx = blockIdx.x * blockDim.x + threadIdx.x;
    if (idx >= BATCH * C3 * 49) return;
    int c = (idx / 49) % C3;
    float mean = d_s3[c] * invN;
    float var = d_q3[c] * invN - mean * mean;
    float rstd = rsqrtf(var + EPSF);
    float scale = __ldg(&g[c]) * rstd;
    float shift = __ldg(&bb[c]) - mean * scale;
    float v = (scale >= 0.f) ? d_p3max[idx] : d_p3min[idx];
    float r = fmaxf(fmaf(v, scale, shift), 0.f);
    int b = idx / (C3 * 49), rr = idx % (C3 * 49);
    d_feat[(long)b * FEAT + rr] = r;
}

// ---------------- LocallyConnected2d (float4 weight loads) --------------------
#define LC_BT 4
__global__ void lc_kernel(const float* __restrict__ w, const float* __restrict__ bias) {
    __shared__ float sh[LC_BT * 2940];
    int b0 = blockIdx.x * LC_BT;
    int t = threadIdx.x;  // 0..239
    for (int idx = t; idx < LC_BT * 2940; idx += 240) {
        int bb = idx / 2940, off = idx % 2940;
        sh[idx] = d_feat[(long)(b0 + bb) * FEAT + off];
    }
    __syncthreads();
    int go = blockIdx.y * 240 + t;  // 0..2879
    int o = go / 36, ij = go % 36, i = ij / 6, j = ij % 6;
    float bv = __ldg(&bias[o * 36 + ij]);
    float acc[LC_BT];
#pragma unroll
    for (int bb = 0; bb < LC_BT; bb++) acc[bb] = bv;
    // wp + c*144 is 16B-aligned (ij*4 floats offset), 4 weights contiguous
    const float* wp = w + (long)o * 60 * 144 + ij * 4;
    for (int c = 0; c < 60; c++) {
        int hb = c * 49 + i * 7 + j;
        float4 wv = __ldg((const float4*)(wp + c * 144));
#pragma unroll
        for (int bb = 0; bb < LC_BT; bb++) {
            const float* hp = sh + bb * 2940 + hb;
            acc[bb] += hp[0] * wv.x + hp[1] * wv.y + hp[7] * wv.z + hp[8] * wv.w;
        }
    }
    float ps = 0.f, pq = 0.f;
#pragma unroll
    for (int bb = 0; bb < LC_BT; bb++) {
        d_lc[((long)(b0 + bb) * CL + o) * 36 + ij] = acc[bb];
        ps += acc[bb];
        pq += acc[bb] * acc[bb];
    }
    atomicAdd(&d_s4[o], ps);
    atomicAdd(&d_q4[o], pq);
}

__global__ void lcbn_kernel(const float* __restrict__ g, const float* __restrict__ bb) {
    int idx = blockIdx.x * blockDim.x + threadIdx.x;
    if (idx >= BATCH * CL * 36) return;
    int b = idx / (CL * 36), r = idx % (CL * 36), o = r / 36;
    const float invN = 1.f / (BATCH * 36);
    float mean = d_s4[o] * invN;
    float var = d_q4[o] * invN - mean * mean;
    float rstd = rsqrtf(var + EPSF);
    float scale = __ldg(&g[o]) * rstd;
    float shift = __ldg(&bb[o]) - mean * scale;
    d_feat[(long)b * FEAT + X2OFF + r] = fmaxf(fmaf(d_lc[idx], scale, shift), 0.f);
}

// ---------------- FC: split-K GEMM, 64x64 tiles, 4x4 microtile, double-buffer -
__global__ void __launch_bounds__(256) fc_kernel(const float* __restrict__ fw) {
    __shared__ float As[2][32][68];
    __shared__ float Bs[2][32][68];
    int n0 = blockIdx.x * 64, m0 = blockIdx.y * 64;
    int kz = blockIdx.z;
    int kstart = kz * KCHUNK;
    int kend = min(FEAT, kstart + KCHUNK);
    int tid = threadIdx.x;
    int tx = tid % 16, ty = tid / 16;

    float acc[4][4];
#pragma unroll
    for (int i = 0; i < 4; i++)
#pragma unroll
        for (int j = 0; j < 4; j++) acc[i][j] = 0.f;

    int lr = tid / 8;        // 0..31
    int lk = (tid % 8) * 4;  // 0..28

    {
        int kk = kstart + lk;
        bool kok = (kk < kend);
#pragma unroll
        for (int half = 0; half < 2; half++) {
            int r = lr + half * 32;
            float4 av = kok ? *(const float4*)&d_feat[(long)(m0 + r) * FEAT + kk]
                            : make_float4(0.f, 0.f, 0.f, 0.f);
            float4 bv = kok ? *(const float4*)&fw[(long)(n0 + r) * FEAT + kk]
                            : make_float4(0.f, 0.f, 0.f, 0.f);
            As[0][lk + 0][r] = av.x; As[0][lk + 1][r] = av.y;
            As[0][lk + 2][r] = av.z; As[0][lk + 3][r] = av.w;
            Bs[0][lk + 0][r] = bv.x; Bs[0][lk + 1][r] = bv.y;
            Bs[0][lk + 2][r] = bv.z; Bs[0][lk + 3][r] = bv.w;
        }
    }
    __syncthreads();

    int buf = 0;
    for (int k0 = kstart; k0 < kend; k0 += 32) {
        int nk0 = k0 + 32;
        bool has = (nk0 < kend);
        float4 pav[2], pbv[2];
        if (has) {
            int kk = nk0 + lk;
            bool kok = (kk < kend);
#pragma unroll
            for (int half = 0; half < 2; half++) {
                int r = lr + half * 32;
                pav[half] = kok ? *(const float4*)&d_feat[(long)(m0 + r) * FEAT + kk]
                                : make_float4(0.f, 0.f, 0.f, 0.f);
                pbv[half] = kok ? *(const float4*)&fw[(long)(n0 + r) * FEAT + kk]
                                : make_float4(0.f, 0.f, 0.f, 0.f);
            }
        }
#pragma unroll
        for (int k = 0; k < 32; k++) {
            float4 a = *(const float4*)&As[buf][k][ty * 4];
            float4 b = *(const float4*)&Bs[buf][k][tx * 4];
            acc[0][0] += a.x * b.x; acc[0][1] += a.x * b.y; acc[0][2] += a.x * b.z; acc[0][3] += a.x * b.w;
            acc[1][0] += a.y * b.x; acc[1][1] += a.y * b.y; acc[1][2] += a.y * b.z; acc[1][3] += a.y * b.w;
            acc[2][0] += a.z * b.x; acc[2][1] += a.z * b.y; acc[2][2] += a.z * b.z; acc[2][3] += a.z * b.w;
            acc[3][0] += a.w * b.x; acc[3][1] += a.w * b.y; acc[3][2] += a.w * b.z; acc[3][3] += a.w * b.w;
        }
        if (has) {
            int nb = buf ^ 1;
#pragma unroll
            for (int half = 0; half < 2; half++) {
                int r = lr + half * 32;
                As[nb][lk + 0][r] = pav[half].x; As[nb][lk + 1][r] = pav[half].y;
                As[nb][lk + 2][r] = pav[half].z; As[nb][lk + 3][r] = pav[half].w;
                Bs[nb][lk + 0][r] = pbv[half].x; Bs[nb][lk + 1][r] = pbv[half].y;
                Bs[nb][lk + 2][r] = pbv[half].z; Bs[nb][lk + 3][r] = pbv[half].w;
            }
        }
        __syncthreads();
        buf ^= 1;
    }
    float* yp = d_ypart + (long)kz * BATCH * NFC;
#pragma unroll
    for (int i = 0; i < 4; i++) {
        int m = m0 + ty * 4 + i;
#pragma unroll
        for (int j = 0; j < 4; j++)
            yp[(long)m * NFC + n0 + tx * 4 + j] = acc[i][j];
    }
}

__global__ void fc_combine_kernel(const float* __restrict__ fb) {
    int idx = blockIdx.x * blockDim.x + threadIdx.x;
    if (idx >= BATCH * NFC) return;
    int n = idx % NFC;
    float v = __ldg(&fb[n]);
#pragma unroll
    for (int kz = 0; kz < KSPLIT; kz++)
        v += d_ypart[(long)kz * BATCH * NFC + idx];
    d_y[idx] = v;
    atomicAdd(&d_s5[n], v);
    atomicAdd(&d_q5[n], v * v);
}

__global__ void fuse_kernel(const float* __restrict__ g, const float* __restrict__ bb,
                            const float* __restrict__ fw, const float* __restrict__ fbias,
                            float* __restrict__ out) {
    int idx = blockIdx.x * blockDim.x + threadIdx.x;
    if (idx >= BATCH * HASHN) return;
    int b = idx / HASHN, h = idx % HASHN;
    float acc = __ldg(&fbias[h]);
    const float invN = 1.f / BATCH;
#pragma unroll
    for (int s = 0; s < SPLITN; s++) {
        int f = h * SPLITN + s;
        float mean = d_s5[f] * invN;
        float var = d_q5[f] * invN - mean * mean;
        float rstd = rsqrtf(var + EPSF);
        float scale = __ldg(&g[f]) * rstd;
        float shift = __ldg(&bb[f]) - mean * scale;
        float v = fmaxf(fmaf(d_y[(long)b * NFC + f], scale, shift), 0.f);
        acc += v * __ldg(&fw[h * SPLITN + s]);
    }
    out[idx] = acc;
}

// ---------------- launch ------------------------------------------------------
extern "C" void kernel_launch(void* const* d_in, const int* in_sizes, int n_in,
                              void* d_out, int out_size) {
    const float* x = (const float*)d_in[0];
    const float* c1w = (const float*)d_in[1];
    const float* c1b = (const float*)d_in[2];
    const float* g1 = (const float*)d_in[3];
    const float* b1 = (const float*)d_in[4];
    const float* c2w = (const float*)d_in[5];
    const float* c2b = (const float*)d_in[6];
    const float* g2 = (const float*)d_in[7];
    const float* b2 = (const float*)d_in[8];
    const float* c3w = (const float*)d_in[9];
    const float* c3b = (const float*)d_in[10];
    const float* g3 = (const float*)d_in[11];
    const float* b3 = (const float*)d_in[12];
    const float* lcw = (const float*)d_in[13];
    const float* lcb = (const float*)d_in[14];
    const float* g4 = (const float*)d_in[15];
    const float* b4 = (const float*)d_in[16];
    const float* fcw = (const float*)d_in[17];
    const float* fcb = (const float*)d_in[18];
    const float* g5 = (const float*)d_in[19];
    const float* b5 = (const float*)d_in[20];
    const float* fw = (const float*)d_in[21];
    const float* fbias = (const float*)d_in[22];
    float* out = (float*)d_out;

    zero_stats_kernel<<<1, 1024>>>();

    // conv1: 992 tiles, 2 co-groups of 10
    conv1_kernel<<<dim3(4, 2, BATCH), 256>>>(x, c1w, c1b);
    // conv2 (applies bn1 on input): 450 2-row tiles, 4 co-groups of 10
    conv2x2_kernel<2><<<dim3(2, 4, BATCH), 256>>>(c2w, c2b, g1, b1);
    // conv3 (applies bn2 on input): 98 2-row tiles, 5 co-groups of 12, 2 imgs/block
    conv2x2_kernel<3><<<dim3(1, 5, BATCH / 2), 224>>>(c3w, c3b, g2, b2);
    // bn3 -> feat x1
    bnapply3_kernel<<<(BATCH * C3 * 49 + 255) / 256, 256>>>(g3, b3);

    lc_kernel<<<dim3(BATCH / LC_BT, 12), 240>>>(lcw, lcb);
    lcbn_kernel<<<(BATCH * CL * 36 + 255) / 256, 256>>>(g4, b4);

    // FC gemm: 64x64 tiles, 4x4 microtile, split-K 8, double-buffered
    fc_kernel<<<dim3(NFC / 64, BATCH / 64, KSPLIT), 256>>>(fcw);
    fc_combine_kernel<<<(BATCH * NFC + 255) / 256, 256>>>(fcb);
    fuse_kernel<<<(BATCH * HASHN + 255) / 256, 256>>>(g5, b5, fw, fbias, out);
}